// round 2
// baseline (speedup 1.0000x reference)
#include <cuda_runtime.h>

#define F    13
#define MSG  32
#define HID  64
#define INE  34
#define INEP 36
#define BB   4
#define NL   20000
#define NH   100000
#define NE   800000
#define TOT_E (BB*NE)     /* 3,200,000 */
#define TOT_N (BB*NH)     /* 400,000  */
#define INN  45
#define INNP 48
#define FOP  16

typedef unsigned long long ull;

// 51.2 MB scatter-add scratch (device global: allocation-free scratch)
__device__ __align__(16) float g_agg[(size_t)TOT_N * MSG];

__device__ __forceinline__ ull pk(float lo, float hi) {
    ull r; asm("mov.b64 %0, {%1,%2};" : "=l"(r) : "f"(lo), "f"(hi)); return r;
}
__device__ __forceinline__ void upk(ull v, float& lo, float& hi) {
    asm("mov.b64 {%0,%1}, %2;" : "=f"(lo), "=f"(hi) : "l"(v));
}
#define FMA2(d,a,b,c) asm("fma.rn.f32x2 %0, %1, %2, %3;" : "=l"(d) : "l"(a), "l"(b), "l"(c))
#define MUL2(d,a,b)   asm("mul.rn.f32x2 %0, %1, %2;"     : "=l"(d) : "l"(a), "l"(b))
#define ADD2(d,a,b)   asm("add.rn.f32x2 %0, %1, %2;"     : "=l"(d) : "l"(a), "l"(b))

// tanh via MUFU (EX2 + RCP): 1 - 2/(1+exp(2x)).
// ~4 FMA-pipe ops + 2 MUFU per activation; offloads the saturated FMA pipe.
// Handles +-inf naturally (exp->inf => 1, exp->0 => -1).
__device__ __forceinline__ float tanh1(float x) {
    float e = __expf(x + x);
    float r = __fdividef(2.0f, e + 1.0f);
    return 1.0f - r;
}

__device__ __forceinline__ void tanh2(float xa, float xb, float& ra, float& rb) {
    float ea = __expf(xa + xa);
    float eb = __expf(xb + xb);
    ra = 1.0f - __fdividef(2.0f, ea + 1.0f);
    rb = 1.0f - __fdividef(2.0f, eb + 1.0f);
}

__global__ void zero_kernel() {
    size_t i = (size_t)blockIdx.x * blockDim.x + threadIdx.x;
    float4* p = (float4*)g_agg;
    const size_t n = (size_t)TOT_N * MSG / 4;
    const size_t step = (size_t)gridDim.x * blockDim.x;
    for (; i < n; i += step)
        p[i] = make_float4(0.f, 0.f, 0.f, 0.f);
}

__global__ void __launch_bounds__(128, 3) edge_kernel(
    const float* __restrict__ z_l, const float* __restrict__ z_h,
    const int* __restrict__ src, const int* __restrict__ tgt,
    const float* __restrict__ We1, const float* __restrict__ be1,
    const float* __restrict__ We2, const float* __restrict__ be2,
    const float* __restrict__ Ww1, const float* __restrict__ bw1,
    const float* __restrict__ Ww2, const float* __restrict__ bw2)
{
    __shared__ __align__(16) float sWe1[HID][INEP];
    __shared__ __align__(16) float sWw1[HID][INEP];
    __shared__ __align__(16) float sWe2[HID * MSG];
    __shared__ float sWw2[HID], sbe1[HID], sbw1[HID], sbe2[MSG], sbw2;

    for (int i = threadIdx.x; i < HID * INEP; i += 128) {
        ((float*)sWe1)[i] = 0.f;
        ((float*)sWw1)[i] = 0.f;
    }
    __syncthreads();
    for (int i = threadIdx.x; i < INE * HID; i += 128) {
        int k = i / HID, h = i % HID;           // We1 is (INE, HID) row-major
        sWe1[h][k] = We1[i];
        sWw1[h][k] = Ww1[i];
    }
    for (int i = threadIdx.x; i < HID * MSG; i += 128) sWe2[i] = We2[i];
    if (threadIdx.x < HID) {
        sWw2[threadIdx.x] = Ww2[threadIdx.x];
        sbe1[threadIdx.x] = be1[threadIdx.x];
        sbw1[threadIdx.x] = bw1[threadIdx.x];
    }
    if (threadIdx.x < MSG) sbe2[threadIdx.x] = be2[threadIdx.x];
    if (threadIdx.x == 0) sbw2 = bw2[0];
    __syncthreads();

    int idx = blockIdx.x * 128 + threadIdx.x;
    if (idx >= TOT_E) return;
    int b = idx / NE;
    int s = src[idx];
    int t = tgt[idx];
    const float* zs = z_l + ((size_t)b * NL + s) * F;
    const float* zt = z_h + ((size_t)b * NH + t) * F;

    float in[INEP];
#pragma unroll
    for (int i = 0; i < F; i++) in[i] = zs[i];
#pragma unroll
    for (int i = 0; i < F; i++) in[F + i] = zt[i];
    float dx = in[0] - in[13], dy = in[1] - in[14], dz = in[2] - in[15];
    in[26] = dx; in[27] = dy; in[28] = dz;
    in[29] = dx * dx + dy * dy + dz * dz;                 // squared dist (no sqrt)
    float ax = in[3], ay = in[4], az = in[5];
    float bx = in[16], by = in[17], bz = in[18];
    float cx = ay * bz - az * by;
    float cy = az * bx - ax * bz;
    float cz = ax * by - ay * bx;
    in[30] = cx; in[31] = cy; in[32] = cz;
    in[33] = sqrtf(cx * cx + cy * cy + cz * cz);
    in[34] = 0.f; in[35] = 0.f;

    ull inp2[INEP / 2];
#pragma unroll
    for (int k = 0; k < INEP / 2; k++) inp2[k] = pk(in[2 * k], in[2 * k + 1]);

    ull m2[MSG / 2];
#pragma unroll
    for (int j = 0; j < MSG / 2; j++) m2[j] = pk(sbe2[2 * j], sbe2[2 * j + 1]);
    float wsum = sbw2;

#pragma unroll 2
    for (int h = 0; h < HID; h++) {
        const ulonglong2* we = (const ulonglong2*)&sWe1[h][0];
        const ulonglong2* ww = (const ulonglong2*)&sWw1[h][0];
        ull aE0 = 0, aE1 = 0, aW0 = 0, aW1 = 0;
#pragma unroll
        for (int q = 0; q < 9; q++) {
            ulonglong2 a = we[q];
            ulonglong2 c = ww[q];
            FMA2(aE0, a.x, inp2[2 * q],     aE0);
            FMA2(aE1, a.y, inp2[2 * q + 1], aE1);
            FMA2(aW0, c.x, inp2[2 * q],     aW0);
            FMA2(aW1, c.y, inp2[2 * q + 1], aW1);
        }
        ADD2(aE0, aE0, aE1);
        ADD2(aW0, aW0, aW1);
        float e0, e1, w0, w1;
        upk(aE0, e0, e1);
        upk(aW0, w0, w1);
        float xE = e0 + e1 + sbe1[h];
        float xW = w0 + w1 + sbw1[h];
        float he, hw;
        tanh2(xE, xW, he, hw);
        ull hp = pk(he, he);
        const ulonglong2* w2 = (const ulonglong2*)&sWe2[h * MSG];
#pragma unroll
        for (int q = 0; q < 8; q++) {
            ulonglong2 a = w2[q];
            FMA2(m2[2 * q],     hp, a.x, m2[2 * q]);
            FMA2(m2[2 * q + 1], hp, a.y, m2[2 * q + 1]);
        }
        wsum = fmaf(hw, sWw2[h], wsum);
    }

    float w = __fdividef(1.f, 1.f + __expf(-wsum));       // sigmoid
    ull wp = pk(w, w);
    float* aggp = g_agg + ((size_t)b * NH + t) * MSG;
#pragma unroll
    for (int q = 0; q < 8; q++) {
        ull v0 = m2[2 * q], v1 = m2[2 * q + 1];
        MUL2(v0, v0, wp);
        MUL2(v1, v1, wp);
        float f0, f1, f2, f3;
        upk(v0, f0, f1);
        upk(v1, f2, f3);
        asm volatile("red.global.add.v4.f32 [%0], {%1,%2,%3,%4};"
                     :: "l"(aggp + q * 4), "f"(f0), "f"(f1), "f"(f2), "f"(f3)
                     : "memory");
    }
}

__global__ void __launch_bounds__(128, 4) node_kernel(
    const float* __restrict__ z_h,
    const float* __restrict__ Wn1, const float* __restrict__ bn1,
    const float* __restrict__ Wn2, const float* __restrict__ bn2,
    float* __restrict__ out)
{
    __shared__ __align__(16) float sW1[HID][INNP];
    __shared__ __align__(16) float sW2[HID][FOP];
    __shared__ float sb1[HID];
    __shared__ __align__(16) float sb2[FOP];

    for (int i = threadIdx.x; i < HID * INNP; i += 128) ((float*)sW1)[i] = 0.f;
    for (int i = threadIdx.x; i < HID * FOP; i += 128)  ((float*)sW2)[i] = 0.f;
    if (threadIdx.x < FOP) sb2[threadIdx.x] = 0.f;
    __syncthreads();
    for (int i = threadIdx.x; i < INN * HID; i += 128) {
        int k = i / HID, h = i % HID;           // Wn1 is (INN, HID)
        sW1[h][k] = Wn1[i];
    }
    for (int i = threadIdx.x; i < HID * F; i += 128) {
        int h = i / F, j = i % F;               // Wn2 is (HID, F)
        sW2[h][j] = Wn2[i];
    }
    if (threadIdx.x < HID) sb1[threadIdx.x] = bn1[threadIdx.x];
    if (threadIdx.x < F)   sb2[threadIdx.x] = bn2[threadIdx.x];
    __syncthreads();

    int idx = blockIdx.x * 128 + threadIdx.x;
    if (idx >= TOT_N) return;

    float in[INNP];
    const float* z = z_h + (size_t)idx * F;
#pragma unroll
    for (int i = 0; i < F; i++) in[i] = z[i];
    const float4* ag = (const float4*)(g_agg + (size_t)idx * MSG);
#pragma unroll
    for (int q = 0; q < 8; q++) {
        float4 v = ag[q];
        in[F + 4 * q + 0] = v.x;
        in[F + 4 * q + 1] = v.y;
        in[F + 4 * q + 2] = v.z;
        in[F + 4 * q + 3] = v.w;
    }
    in[45] = 0.f; in[46] = 0.f; in[47] = 0.f;

    ull inp2[INNP / 2];
#pragma unroll
    for (int k = 0; k < INNP / 2; k++) inp2[k] = pk(in[2 * k], in[2 * k + 1]);

    ull o2[FOP / 2];
#pragma unroll
    for (int j = 0; j < FOP / 2; j++) o2[j] = pk(sb2[2 * j], sb2[2 * j + 1]);

#pragma unroll 2
    for (int h = 0; h < HID; h++) {
        const ulonglong2* wr = (const ulonglong2*)&sW1[h][0];
        ull a0 = 0, a1 = 0;
#pragma unroll
        for (int q = 0; q < 12; q++) {
            ulonglong2 a = wr[q];
            FMA2(a0, a.x, inp2[2 * q],     a0);
            FMA2(a1, a.y, inp2[2 * q + 1], a1);
        }
        ADD2(a0, a0, a1);
        float e0, e1;
        upk(a0, e0, e1);
        float x = e0 + e1 + sb1[h];
        float he = tanh1(x);
        ull hp = pk(he, he);
        const ulonglong2* w2 = (const ulonglong2*)&sW2[h][0];
#pragma unroll
        for (int q = 0; q < 4; q++) {
            ulonglong2 a = w2[q];
            FMA2(o2[2 * q],     hp, a.x, o2[2 * q]);
            FMA2(o2[2 * q + 1], hp, a.y, o2[2 * q + 1]);
        }
    }
    float o[FOP];
#pragma unroll
    for (int j = 0; j < FOP / 2; j++) upk(o2[j], o[2 * j], o[2 * j + 1]);
    float* op = out + (size_t)idx * F;
#pragma unroll
    for (int j = 0; j < F; j++) op[j] = o[j];
}

extern "C" void kernel_launch(void* const* d_in, const int* in_sizes, int n_in,
                              void* d_out, int out_size)
{
    const float* z_l = (const float*)d_in[0];
    const float* z_h = (const float*)d_in[1];
    const int*   src = (const int*)d_in[2];
    const int*   tgt = (const int*)d_in[3];
    const float* We1 = (const float*)d_in[4];
    const float* be1 = (const float*)d_in[5];
    const float* We2 = (const float*)d_in[6];
    const float* be2 = (const float*)d_in[7];
    const float* Ww1 = (const float*)d_in[8];
    const float* bw1 = (const float*)d_in[9];
    const float* Ww2 = (const float*)d_in[10];
    const float* bw2 = (const float*)d_in[11];
    const float* Wn1 = (const float*)d_in[12];
    const float* bn1 = (const float*)d_in[13];
    const float* Wn2 = (const float*)d_in[14];
    const float* bn2 = (const float*)d_in[15];
    float* out = (float*)d_out;

    zero_kernel<<<2048, 256>>>();
    edge_kernel<<<TOT_E / 128, 128>>>(z_l, z_h, src, tgt,
                                      We1, be1, We2, be2,
                                      Ww1, bw1, Ww2, bw2);
    node_kernel<<<TOT_N / 128, 128>>>(z_h, Wn1, bn1, Wn2, bn2, out);
}

// round 5
// speedup vs baseline: 1.1148x; 1.1148x over previous
#include <cuda_runtime.h>

#define F    13
#define MSG  32
#define HID  64
#define INE  34
#define INEP 36
#define BB   4
#define NL   20000
#define NH   100000
#define NE   800000
#define TOT_E (BB*NE)     /* 3,200,000 */
#define TOT_N (BB*NH)     /* 400,000  */
#define INN  45
#define INNP 48
#define FOP  16

typedef unsigned long long ull;

// 51.2 MB scatter-add scratch (device global: allocation-free scratch)
__device__ __align__(16) float g_agg[(size_t)TOT_N * MSG];

__device__ __forceinline__ ull pk(float lo, float hi) {
    ull r; asm("mov.b64 %0, {%1,%2};" : "=l"(r) : "f"(lo), "f"(hi)); return r;
}
__device__ __forceinline__ void upk(ull v, float& lo, float& hi) {
    asm("mov.b64 {%0,%1}, %2;" : "=f"(lo), "=f"(hi) : "l"(v));
}
#define FMA2(d,a,b,c) asm("fma.rn.f32x2 %0, %1, %2, %3;" : "=l"(d) : "l"(a), "l"(b), "l"(c))
#define MUL2(d,a,b)   asm("mul.rn.f32x2 %0, %1, %2;"     : "=l"(d) : "l"(a), "l"(b))
#define ADD2(d,a,b)   asm("add.rn.f32x2 %0, %1, %2;"     : "=l"(d) : "l"(a), "l"(b))

// tanh via MUFU (EX2 + RCP): 1 - 2/(1+exp(2x)). Offloads the saturated FMA pipe.
// Handles large |x| naturally (exp->inf => 1, exp->0 => -1).
__device__ __forceinline__ float tanhr(float x) {
    float e = __expf(x + x);
    return 1.0f - __fdividef(2.0f, e + 1.0f);
}
__device__ __forceinline__ void tanh2(float xa, float xb, float& ra, float& rb) {
    float ea = __expf(xa + xa);
    float eb = __expf(xb + xb);
    ra = 1.0f - __fdividef(2.0f, ea + 1.0f);
    rb = 1.0f - __fdividef(2.0f, eb + 1.0f);
}

__global__ void zero_kernel() {
    size_t i = (size_t)blockIdx.x * blockDim.x + threadIdx.x;
    float4* p = (float4*)g_agg;
    const size_t n = (size_t)TOT_N * MSG / 4;
    const size_t step = (size_t)gridDim.x * blockDim.x;
    for (; i < n; i += step)
        p[i] = make_float4(0.f, 0.f, 0.f, 0.f);
}

__global__ void __launch_bounds__(128, 4) edge_kernel(
    const float* __restrict__ z_l, const float* __restrict__ z_h,
    const int* __restrict__ src, const int* __restrict__ tgt,
    const float* __restrict__ We1, const float* __restrict__ be1,
    const float* __restrict__ We2, const float* __restrict__ be2,
    const float* __restrict__ Ww1, const float* __restrict__ bw1,
    const float* __restrict__ Ww2, const float* __restrict__ bw2)
{
    __shared__ __align__(16) float sWe1[HID][INEP];
    __shared__ __align__(16) float sWw1[HID][INEP];
    __shared__ __align__(16) float sWe2[HID * MSG];
    __shared__ float sWw2[HID], sbe1[HID], sbw1[HID], sbe2[MSG], sbw2;

    for (int i = threadIdx.x; i < INE * HID; i += 128) {
        int k = i / HID, h = i % HID;           // We1 is (INE, HID) row-major
        sWe1[h][k] = We1[i];
        sWw1[h][k] = Ww1[i];
    }
    for (int i = threadIdx.x; i < HID * MSG; i += 128) sWe2[i] = We2[i];
    if (threadIdx.x < HID) {
        sWw2[threadIdx.x] = Ww2[threadIdx.x];
        sbe1[threadIdx.x] = be1[threadIdx.x];
        sbw1[threadIdx.x] = bw1[threadIdx.x];
    }
    if (threadIdx.x < MSG) sbe2[threadIdx.x] = be2[threadIdx.x];
    if (threadIdx.x == 0) sbw2 = bw2[0];
    __syncthreads();

    int idx = blockIdx.x * 128 + threadIdx.x;
    if (idx >= TOT_E) return;
    int b = idx / NE;
    int s = src[idx];
    int t = tgt[idx];
    const float* zs = z_l + ((size_t)b * NL + s) * F;
    const float* zt = z_h + ((size_t)b * NH + t) * F;

    float in[INE];
#pragma unroll
    for (int i = 0; i < F; i++) in[i] = zs[i];
#pragma unroll
    for (int i = 0; i < F; i++) in[F + i] = zt[i];
    float dx = in[0] - in[13], dy = in[1] - in[14], dz = in[2] - in[15];
    in[26] = dx; in[27] = dy; in[28] = dz;
    in[29] = dx * dx + dy * dy + dz * dz;                 // squared dist (no sqrt)
    float ax = in[3], ay = in[4], az = in[5];
    float bx = in[16], by = in[17], bz = in[18];
    float cx = ay * bz - az * by;
    float cy = az * bx - ax * bz;
    float cz = ax * by - ay * bx;
    in[30] = cx; in[31] = cy; in[32] = cz;
    in[33] = sqrtf(cx * cx + cy * cy + cz * cz);

    ull inp2[17];
#pragma unroll
    for (int k = 0; k < 17; k++) inp2[k] = pk(in[2 * k], in[2 * k + 1]);

    ull m2[MSG / 2];
#pragma unroll
    for (int j = 0; j < MSG / 2; j++) m2[j] = pk(sbe2[2 * j], sbe2[2 * j + 1]);
    float wsum = sbw2;

#pragma unroll 1
    for (int h = 0; h < HID; h++) {
        const ulonglong2* we = (const ulonglong2*)&sWe1[h][0];
        const ulonglong2* ww = (const ulonglong2*)&sWw1[h][0];
        // bias folded into accumulator init (lane 0)
        ull aE0 = pk(sbe1[h], 0.f), aE1 = 0;
        ull aW0 = pk(sbw1[h], 0.f), aW1 = 0;
#pragma unroll
        for (int q = 0; q < 8; q++) {
            ulonglong2 a = we[q];
            ulonglong2 c = ww[q];
            FMA2(aE0, a.x, inp2[2 * q],     aE0);
            FMA2(aE1, a.y, inp2[2 * q + 1], aE1);
            FMA2(aW0, c.x, inp2[2 * q],     aW0);
            FMA2(aW1, c.y, inp2[2 * q + 1], aW1);
        }
        {   // tail pair (k = 32,33)
            ull wt = ((const ull*)&sWe1[h][0])[16];
            ull ct = ((const ull*)&sWw1[h][0])[16];
            FMA2(aE0, wt, inp2[16], aE0);
            FMA2(aW0, ct, inp2[16], aW0);
        }
        ADD2(aE0, aE0, aE1);
        ADD2(aW0, aW0, aW1);
        float e0, e1, w0, w1;
        upk(aE0, e0, e1);
        upk(aW0, w0, w1);
        float xE = e0 + e1;
        float xW = w0 + w1;
        float he, hw;
        tanh2(xE, xW, he, hw);
        ull hp = pk(he, he);
        const ulonglong2* w2 = (const ulonglong2*)&sWe2[h * MSG];
#pragma unroll
        for (int q = 0; q < 8; q++) {
            ulonglong2 a = w2[q];
            FMA2(m2[2 * q],     hp, a.x, m2[2 * q]);
            FMA2(m2[2 * q + 1], hp, a.y, m2[2 * q + 1]);
        }
        wsum = fmaf(hw, sWw2[h], wsum);
    }

    float w = __fdividef(1.f, 1.f + __expf(-wsum));       // sigmoid
    ull wp = pk(w, w);
    float* aggp = g_agg + ((size_t)b * NH + t) * MSG;
#pragma unroll
    for (int q = 0; q < 8; q++) {
        ull v0 = m2[2 * q], v1 = m2[2 * q + 1];
        MUL2(v0, v0, wp);
        MUL2(v1, v1, wp);
        float f0, f1, f2, f3;
        upk(v0, f0, f1);
        upk(v1, f2, f3);
        asm volatile("red.global.add.v4.f32 [%0], {%1,%2,%3,%4};"
                     :: "l"(aggp + q * 4), "f"(f0), "f"(f1), "f"(f2), "f"(f3)
                     : "memory");
    }
}

__global__ void __launch_bounds__(128, 4) node_kernel(
    const float* __restrict__ z_h,
    const float* __restrict__ Wn1, const float* __restrict__ bn1,
    const float* __restrict__ Wn2, const float* __restrict__ bn2,
    float* __restrict__ out)
{
    __shared__ __align__(16) float sW1[HID][INNP];
    __shared__ __align__(16) float sW2[HID][FOP];
    __shared__ float sb1[HID];
    __shared__ __align__(16) float sb2[FOP];

    for (int i = threadIdx.x; i < HID * INNP; i += 128) ((float*)sW1)[i] = 0.f;
    for (int i = threadIdx.x; i < HID * FOP; i += 128)  ((float*)sW2)[i] = 0.f;
    if (threadIdx.x < FOP) sb2[threadIdx.x] = 0.f;
    __syncthreads();
    for (int i = threadIdx.x; i < INN * HID; i += 128) {
        int k = i / HID, h = i % HID;           // Wn1 is (INN, HID)
        sW1[h][k] = Wn1[i];
    }
    for (int i = threadIdx.x; i < HID * F; i += 128) {
        int h = i / F, j = i % F;               // Wn2 is (HID, F)
        sW2[h][j] = Wn2[i];
    }
    if (threadIdx.x < HID) sb1[threadIdx.x] = bn1[threadIdx.x];
    if (threadIdx.x < F)   sb2[threadIdx.x] = bn2[threadIdx.x];
    __syncthreads();

    int idx = blockIdx.x * 128 + threadIdx.x;
    if (idx >= TOT_N) return;

    float in[INNP];
    const float* z = z_h + (size_t)idx * F;
#pragma unroll
    for (int i = 0; i < F; i++) in[i] = z[i];
    const float4* ag = (const float4*)(g_agg + (size_t)idx * MSG);
#pragma unroll
    for (int q = 0; q < 8; q++) {
        float4 v = ag[q];
        in[F + 4 * q + 0] = v.x;
        in[F + 4 * q + 1] = v.y;
        in[F + 4 * q + 2] = v.z;
        in[F + 4 * q + 3] = v.w;
    }
    in[45] = 0.f; in[46] = 0.f; in[47] = 0.f;

    ull inp2[INNP / 2];
#pragma unroll
    for (int k = 0; k < INNP / 2; k++) inp2[k] = pk(in[2 * k], in[2 * k + 1]);

    ull o2[FOP / 2];
#pragma unroll
    for (int j = 0; j < FOP / 2; j++) o2[j] = pk(sb2[2 * j], sb2[2 * j + 1]);

#pragma unroll 1
    for (int h = 0; h < HID; h++) {
        const ulonglong2* wr = (const ulonglong2*)&sW1[h][0];
        ull a0 = pk(sb1[h], 0.f), a1 = 0;
#pragma unroll
        for (int q = 0; q < 12; q++) {
            ulonglong2 a = wr[q];
            FMA2(a0, a.x, inp2[2 * q],     a0);
            FMA2(a1, a.y, inp2[2 * q + 1], a1);
        }
        ADD2(a0, a0, a1);
        float e0, e1;
        upk(a0, e0, e1);
        float x = e0 + e1;
        float he = tanhr(x);
        ull hp = pk(he, he);
        const ulonglong2* w2 = (const ulonglong2*)&sW2[h][0];
#pragma unroll
        for (int q = 0; q < 4; q++) {
            ulonglong2 a = w2[q];
            FMA2(o2[2 * q],     hp, a.x, o2[2 * q]);
            FMA2(o2[2 * q + 1], hp, a.y, o2[2 * q + 1]);
        }
    }
    float o[FOP];
#pragma unroll
    for (int j = 0; j < FOP / 2; j++) upk(o2[j], o[2 * j], o[2 * j + 1]);
    float* op = out + (size_t)idx * F;
#pragma unroll
    for (int j = 0; j < F; j++) op[j] = o[j];
}

extern "C" void kernel_launch(void* const* d_in, const int* in_sizes, int n_in,
                              void* d_out, int out_size)
{
    const float* z_l = (const float*)d_in[0];
    const float* z_h = (const float*)d_in[1];
    const int*   src = (const int*)d_in[2];
    const int*   tgt = (const int*)d_in[3];
    const float* We1 = (const float*)d_in[4];
    const float* be1 = (const float*)d_in[5];
    const float* We2 = (const float*)d_in[6];
    const float* be2 = (const float*)d_in[7];
    const float* Ww1 = (const float*)d_in[8];
    const float* bw1 = (const float*)d_in[9];
    const float* Ww2 = (const float*)d_in[10];
    const float* bw2 = (const float*)d_in[11];
    const float* Wn1 = (const float*)d_in[12];
    const float* bn1 = (const float*)d_in[13];
    const float* Wn2 = (const float*)d_in[14];
    const float* bn2 = (const float*)d_in[15];
    float* out = (float*)d_out;

    zero_kernel<<<2048, 256>>>();
    edge_kernel<<<TOT_E / 128, 128>>>(z_l, z_h, src, tgt,
                                      We1, be1, We2, be2,
                                      Ww1, bw1, Ww2, bw2);
    node_kernel<<<TOT_N / 128, 128>>>(z_h, Wn1, bn1, Wn2, bn2, out);
}